// round 3
// baseline (speedup 1.0000x reference)
#include <cuda_runtime.h>
#include <cstdint>

#define BB 64
#define SS 196
#define HALFS 98
#define OO 10
#define SLAB 4096           // float2 per 64x64 slab
#define SLAB_BYTES 32768

__device__ __align__(128) float2 g_coresT[SS * SLAB];
__device__ float g_vecL[BB][64];
__device__ float g_vecR[BB][64];

// ---------------------------------------------------------------------------
__device__ __forceinline__ uint32_t smem_u32(const void* p) {
    uint32_t a;
    asm("{ .reg .u64 t; cvta.to.shared.u64 t, %1; cvt.u32.u64 %0, t; }"
        : "=r"(a) : "l"(p));
    return a;
}
__device__ __forceinline__ void mbar_init(uint32_t a, uint32_t cnt) {
    asm volatile("mbarrier.init.shared.b64 [%0], %1;" :: "r"(a), "r"(cnt) : "memory");
}
__device__ __forceinline__ void mbar_arrive(uint32_t a) {
    asm volatile("mbarrier.arrive.shared.b64 _, [%0];" :: "r"(a) : "memory");
}
__device__ __forceinline__ void mbar_expect_tx(uint32_t a, uint32_t bytes) {
    asm volatile("mbarrier.arrive.expect_tx.shared.b64 _, [%0], %1;"
                 :: "r"(a), "r"(bytes) : "memory");
}
__device__ __forceinline__ void mbar_wait(uint32_t a, uint32_t phase) {
    asm volatile(
        "{\n\t.reg .pred P;\n\t"
        "W_%=:\n\t"
        "mbarrier.try_wait.parity.shared.b64 P, [%0], %1;\n\t"
        "@!P bra W_%=;\n\t}"
        :: "r"(a), "r"(phase) : "memory");
}
__device__ __forceinline__ void bulk_g2s(uint32_t dst, const void* src,
                                         uint32_t bytes, uint32_t mbar) {
    asm volatile(
        "cp.async.bulk.shared::cluster.global.mbarrier::complete_tx::bytes "
        "[%0], [%1], %2, [%3];"
        :: "r"(dst), "l"(src), "r"(bytes), "r"(mbar) : "memory");
}

// ---------------------------------------------------------------------------
// Kernel 1: per-s 64x64 float2 transpose, MLP-16 front-batched loads.
// ---------------------------------------------------------------------------
__global__ __launch_bounds__(256) void transpose_kernel(const float2* __restrict__ cores)
{
    __shared__ float2 tile[64][65];
    const int s = blockIdx.x;
    const float2* src = cores + (size_t)s * SLAB;
    float2* dst = g_coresT + (size_t)s * SLAB;
    const int t = threadIdx.x;

    float2 v[16];
#pragma unroll
    for (int i = 0; i < 16; i++) v[i] = src[t + i * 256];      // MLP=16
#pragma unroll
    for (int i = 0; i < 16; i++) {
        int idx = t + i * 256;
        tile[idx >> 6][idx & 63] = v[i];
    }
    __syncthreads();
#pragma unroll
    for (int i = 0; i < 16; i++) {
        int idx = t + i * 256;
        v[i] = tile[idx & 63][idx >> 6];
    }
#pragma unroll
    for (int i = 0; i < 16; i++) dst[t + i * 256] = v[i];
}

// ---------------------------------------------------------------------------
// Kernel 2: 64 CTAs x 256 threads. CTA = (half, batch-pair b0,b0+1).
// Thread (g = m-quarter, n = column): reads C once, FMAs for BOTH batches.
// C register-double-buffered: step k+1's SMEM reads overlap step k's tail.
// ---------------------------------------------------------------------------
__global__ __launch_bounds__(256, 1) void chain_kernel(const float* __restrict__ x,
                                                       const float2* __restrict__ cores)
{
    extern __shared__ __align__(128) unsigned char dynsm[];
    float2*   Cbuf = (float2*)dynsm;                                  // 4 x 32KB slots
    float4*   part = (float4*)(dynsm + 4 * SLAB_BYTES);               // [4][64]
    float2*   lvb  = (float2*)(dynsm + 4 * SLAB_BYTES + 4096);        // [64] (b0,b1)
    float2*   xsh  = (float2*)(dynsm + 4 * SLAB_BYTES + 4096 + 512);  // [2][98]
    uint64_t* bars = (uint64_t*)(dynsm + 4 * SLAB_BYTES + 4096 + 512 + 2 * HALFS * 8);
    const uint32_t bbase = smem_u32(bars);  // +0/+8 full q0/q1, +16/+24 empty q0/q1
    const uint32_t cb0   = smem_u32(Cbuf);

    const int t = threadIdx.x;
    const int n = t & 63;
    const int g = t >> 6;
    const int half = blockIdx.x >> 5;
    const int b0 = (blockIdx.x & 31) * 2;

    const float2* xf = (const float2*)x;   // [B][S]
    for (int k = t; k < HALFS; k += 256) {
        int s = half ? (SS - 1 - k) : k;
        xsh[k]         = xf[(b0 + 0) * SS + s];
        xsh[HALFS + k] = xf[(b0 + 1) * SS + s];
    }
    if (t < 64) lvb[t] = make_float2(t == 0 ? 1.f : 0.f, t == 0 ? 1.f : 0.f);

    const float2* s0 = half ? (g_coresT + (size_t)(SS - 1) * SLAB) : cores;
    const long sstride = half ? -(long)SLAB : (long)SLAB;

    if (t == 0) {
        mbar_init(bbase + 0, 1);   mbar_init(bbase + 8, 1);    // full
        mbar_init(bbase + 16, 8);  mbar_init(bbase + 24, 8);   // empty (8 warps)
    }
    __syncthreads();

    if (t == 0) {   // prologue: fill pairs 0 (slots 0,1) and 1 (slots 2,3)
        mbar_expect_tx(bbase + 0, 2 * SLAB_BYTES);
        bulk_g2s(cb0 + 0 * SLAB_BYTES, s0 + 0 * sstride, SLAB_BYTES, bbase + 0);
        bulk_g2s(cb0 + 1 * SLAB_BYTES, s0 + 1 * sstride, SLAB_BYTES, bbase + 0);
        mbar_expect_tx(bbase + 8, 2 * SLAB_BYTES);
        bulk_g2s(cb0 + 2 * SLAB_BYTES, s0 + 2 * sstride, SLAB_BYTES, bbase + 8);
        bulk_g2s(cb0 + 3 * SLAB_BYTES, s0 + 3 * sstride, SLAB_BYTES, bbase + 8);
    }

    float2 A[16], Bf[16];
    mbar_wait(bbase + 0, 0);
    {
        const float2* P = Cbuf + g * 1024 + n;
#pragma unroll
        for (int mm = 0; mm < 16; mm++) A[mm] = P[mm * 64];
    }

#define CHAIN_STEP(CUR, NXT, K)                                                 \
    {                                                                           \
        const int kp1 = (K) + 1;                                                \
        if (kp1 < HALFS) {                                                      \
            if ((kp1 & 1) == 0) {                                               \
                int p = kp1 >> 1;                                               \
                mbar_wait(bbase + (p & 1) * 8, (p >> 1) & 1);                   \
            }                                                                   \
            const float2* Ns = Cbuf + (kp1 & 3) * SLAB + g * 1024 + n;          \
            _Pragma("unroll")                                                   \
            for (int mm = 0; mm < 16; mm++) NXT[mm] = Ns[mm * 64];              \
        }                                                                       \
        const float4* lv4 = (const float4*)(lvb + g * 16);                      \
        float sx0 = 0.f, sy0 = 0.f, sx1 = 0.f, sy1 = 0.f;                       \
        _Pragma("unroll")                                                       \
        for (int q = 0; q < 8; q++) {                                           \
            float4 l4 = lv4[q];   /* (lv0[m],lv1[m],lv0[m+1],lv1[m+1]) */       \
            float2 c0 = CUR[2 * q], c1 = CUR[2 * q + 1];                        \
            sx0 = fmaf(l4.x, c0.x, sx0);  sy0 = fmaf(l4.x, c0.y, sy0);          \
            sx1 = fmaf(l4.y, c0.x, sx1);  sy1 = fmaf(l4.y, c0.y, sy1);          \
            sx0 = fmaf(l4.z, c1.x, sx0);  sy0 = fmaf(l4.z, c1.y, sy0);          \
            sx1 = fmaf(l4.w, c1.x, sx1);  sy1 = fmaf(l4.w, c1.y, sy1);          \
        }                                                                       \
        part[g * 64 + n] = make_float4(sx0, sy0, sx1, sy1);                     \
        if (((K) & 1) == 1 && (t & 31) == 0)                                    \
            mbar_arrive(bbase + 16 + (((K) >> 1) & 1) * 8);                     \
        __syncthreads();                                                        \
        if (((K) & 1) == 1 && t == 0) {                                         \
            int p = (K) >> 1;                                                   \
            if (p + 2 < HALFS / 2) {                                            \
                mbar_wait(bbase + 16 + (p & 1) * 8, (p >> 1) & 1);              \
                mbar_expect_tx(bbase + (p & 1) * 8, 2 * SLAB_BYTES);            \
                int k0 = 2 * p + 4;                                             \
                bulk_g2s(cb0 + (k0 & 3) * SLAB_BYTES,                           \
                         s0 + (long)k0 * sstride, SLAB_BYTES,                   \
                         bbase + (p & 1) * 8);                                  \
                bulk_g2s(cb0 + ((k0 + 1) & 3) * SLAB_BYTES,                     \
                         s0 + (long)(k0 + 1) * sstride, SLAB_BYTES,             \
                         bbase + (p & 1) * 8);                                  \
            }                                                                   \
        }                                                                       \
        if (t < 64) {                                                           \
            float4 p0 = part[n], p1 = part[64 + n];                             \
            float4 p2 = part[128 + n], p3 = part[192 + n];                      \
            float Sx0 = (p0.x + p1.x) + (p2.x + p3.x);                          \
            float Sy0 = (p0.y + p1.y) + (p2.y + p3.y);                          \
            float Sx1 = (p0.z + p1.z) + (p2.z + p3.z);                          \
            float Sy1 = (p0.w + p1.w) + (p2.w + p3.w);                          \
            float2 x0 = xsh[(K)], x1 = xsh[HALFS + (K)];                        \
            lvb[n] = make_float2(fmaf(x0.x, Sx0, x0.y * Sy0),                   \
                                 fmaf(x1.x, Sx1, x1.y * Sy1));                  \
        }                                                                       \
        __syncthreads();                                                        \
    }

#pragma unroll 1
    for (int k = 0; k < HALFS; k += 2) {
        CHAIN_STEP(A, Bf, k);
        CHAIN_STEP(Bf, A, k + 1);
    }
#undef CHAIN_STEP

    if (t < 64) {
        float2 v = lvb[n];
        if (half == 0) { g_vecL[b0][n] = v.x; g_vecL[b0 + 1][n] = v.y; }
        else           { g_vecR[b0][n] = v.x; g_vecR[b0 + 1][n] = v.y; }
    }
}

// ---------------------------------------------------------------------------
// Kernel 3: out[b,o] = sum_{l,r} L[b,l] * oc[o,l,r] * R[b,r]
// ---------------------------------------------------------------------------
__global__ __launch_bounds__(64) void out_kernel(const float* __restrict__ oc,
                                                 float* __restrict__ out)
{
    const int b = blockIdx.x;
    const int r = threadIdx.x;
    __shared__ float Ls[64];
    __shared__ float red[2][OO];

    Ls[r] = g_vecL[b][r];
    const float R = g_vecR[b][r];
    __syncthreads();

    for (int o = 0; o < OO; o++) {
        float acc = 0.f;
        const float* m = oc + o * 4096 + r;
#pragma unroll 8
        for (int l = 0; l < 64; l++) acc = fmaf(Ls[l], m[l * 64], acc);
        acc *= R;
#pragma unroll
        for (int off = 16; off; off >>= 1)
            acc += __shfl_down_sync(0xffffffffu, acc, off);
        if ((r & 31) == 0) red[r >> 5][o] = acc;
    }
    __syncthreads();
    if (r < OO) out[b * OO + r] = red[0][r] + red[1][r];
}

// ---------------------------------------------------------------------------
extern "C" void kernel_launch(void* const* d_in, const int* in_sizes, int n_in,
                              void* d_out, int out_size)
{
    const float* x = nullptr;
    const float* cores = nullptr;
    const float* oc = nullptr;
    for (int i = 0; i < n_in; i++) {
        if (in_sizes[i] == BB * SS * 2)         x = (const float*)d_in[i];
        else if (in_sizes[i] == SS * SLAB * 2)  cores = (const float*)d_in[i];
        else if (in_sizes[i] == OO * 4096)      oc = (const float*)d_in[i];
    }

    const int DYN_SMEM = 4 * SLAB_BYTES + 4096 + 512 + 2 * HALFS * 8 + 64;
    cudaFuncSetAttribute(chain_kernel, cudaFuncAttributeMaxDynamicSharedMemorySize, DYN_SMEM);

    transpose_kernel<<<SS, 256>>>((const float2*)cores);
    chain_kernel<<<64, 256, DYN_SMEM>>>(x, (const float2*)cores);
    out_kernel<<<BB, 64>>>(oc, (float*)d_out);
}